// round 17
// baseline (speedup 1.0000x reference)
#include <cuda_runtime.h>
#include <cuda_bf16.h>
#include <math.h>

#define BB   128
#define SS   1024
#define TT   257
#define VV   256
#define EE   128
#define HH   512
#define GG   2048
#define DSTEPS 256
#define NCTA 128
#define NTH  512
#define HB   (HH * BB)

typedef unsigned long long ull;

// ---------------- device globals ----------------
__device__ float g_tabE[VV * GG];
__device__ float g_tabD[VV * GG];
__device__ float g_b1e[GG];
__device__ float g_b1d[GG];
__device__ float g_fcT[HH * VV];                 // [k][v]
__device__ float g_y0T[(size_t)SS * HB];         // encoder L0 outputs, [s][u][b]
__device__ float g_h0TA[HB], g_h0TB[HB];
__device__ float g_h1TA[HB], g_h1TB[HB];
__device__ float g_h1[BB * HH];                  // plain layout for fc
__device__ int   g_tok[BB];
__device__ int   g_cnt[8];
__device__ int   g_gcnt;
__device__ int   g_gen;

// ---------------- smem layout (floats) ----------------
// CTA = 8 units (32 gate-cols) x 64 batch rows. Weights k-major WT[k][32].
#define S_W0   0          // 512*32 = 16384
#define S_WX   16384
#define S_WH   32768
#define S_AS   49152      // 16 warps x 4 bufs x 16k x 4rows = 4096
#define S_GB   53248      // 32 x 66 = 2112 (also fc scratch: needs 1536)
#define S_CS0  55360      // 512
#define S_CS1  55872      // 512
#define S_TKS  56384      // 64 ints
#define S_TOTAL 56448     // 225792 bytes

// ---------------- helpers ----------------
__device__ __forceinline__ ull pk2(float lo, float hi) {
    ull r; asm("mov.b64 %0, {%1, %2};" : "=l"(r) : "f"(lo), "f"(hi)); return r;
}
__device__ __forceinline__ void fma2(ull& d, ull a, ull b) {
    asm("fma.rn.f32x2 %0, %1, %2, %0;" : "+l"(d) : "l"(a), "l"(b));
}
__device__ __forceinline__ void cp16(float* dst_smem, const float* src) {
    unsigned s = (unsigned)__cvta_generic_to_shared(dst_smem);
    asm volatile("cp.async.cg.shared.global [%0], [%1], 16;" :: "r"(s), "l"(src));
}
#define CP_COMMIT() asm volatile("cp.async.commit_group;")
#define CP_WAIT(n)  asm volatile("cp.async.wait_group %0;" :: "n"(n))

// two-level grid barrier: 8 groups x 16 CTAs
__device__ __forceinline__ void gbar() {
    __syncthreads();
    if (threadIdx.x == 0) {
        const int grp = blockIdx.x >> 4;
        volatile int* vgen = &g_gen;
        int gen = *vgen;
        __threadfence();
        if (atomicAdd(&g_cnt[grp], 1) == 15) {
            atomicExch(&g_cnt[grp], 0);
            if (atomicAdd(&g_gcnt, 1) == 7) {
                atomicExch(&g_gcnt, 0);
                __threadfence();
                atomicAdd(&g_gen, 1);
            } else {
                while (*vgen == gen) { }
            }
        } else {
            while (*vgen == gen) { }
        }
        __threadfence();
    }
    __syncthreads();
}

// ---------------- init kernels ----------------
__global__ void table_kernel(float* __restrict__ tab,
                             const float* __restrict__ emb,
                             const float* __restrict__ w_ih,
                             const float* __restrict__ b_ih,
                             const float* __restrict__ b_hh) {
    const int v = blockIdx.x;
    __shared__ float es[EE];
    if (threadIdx.x < EE) es[threadIdx.x] = emb[v * EE + threadIdx.x];
    __syncthreads();
    for (int j = threadIdx.x; j < GG; j += blockDim.x) {
        float a = b_ih[j] + b_hh[j];
        const float* w = w_ih + (size_t)j * EE;
#pragma unroll 8
        for (int e = 0; e < EE; e++) a += es[e] * w[e];
        tab[(size_t)v * GG + j] = a;
    }
}

__global__ void misc_init_kernel(const int* __restrict__ trg,
                                 const float* __restrict__ be_ih1, const float* __restrict__ be_hh1,
                                 const float* __restrict__ bd_ih1, const float* __restrict__ bd_hh1,
                                 const float* __restrict__ fc_w) {
    const int tid = blockIdx.x * blockDim.x + threadIdx.x;
    const int n = gridDim.x * blockDim.x;
    for (int i = tid; i < HB; i += n) {
        g_h0TA[i] = 0.f; g_h0TB[i] = 0.f;
        g_h1TA[i] = 0.f; g_h1TB[i] = 0.f;
    }
    for (int j = tid; j < GG; j += n) {
        g_b1e[j] = be_ih1[j] + be_hh1[j];
        g_b1d[j] = bd_ih1[j] + bd_hh1[j];
    }
    for (int i = tid; i < HH * VV; i += n) {
        int k = i >> 8, v = i & 255;
        g_fcT[i] = fc_w[v * HH + k];
    }
    for (int b = tid; b < BB; b += n) g_tok[b] = trg[b * TT];
}

// ============================================================
// Geometry: CTA = 8 units (32 gate-cols) x 64 rows (b0 half).
// 512 threads = 16 warps; warp = 4 rows x 32 cols; thread =
// 4 rows x 1 col (lane = gate-col). Full K=512 per thread.
// A staged per-warp via 4-deep cp.async ring (16k chunks).
// Weights in smem k-major WT[k][32] (conflict-free scalar LDS).
// ============================================================

// load weight slice transposed: dst[k*32 + c] = W[jrow(c)][k]
__device__ __forceinline__ void load_wsliceT(float* dst, const float* __restrict__ W, int u0) {
    for (int idx = threadIdx.x; idx < 32 * HH; idx += NTH) {
        int c = idx & 31, k = idx >> 5;
        int j = (c >> 3) * HH + u0 + (c & 7);
        dst[k * 32 + c] = W[(size_t)j * HH + k];
    }
}

// stage one 16k x 4row chunk for this warp (lanes 0-15)
__device__ __forceinline__ void stage_w(float* wbuf, const float* __restrict__ srcT,
                                        int kb, int buf, int lane, int gr0) {
    if (lane < 16)
        cp16(wbuf + buf * 64 + lane * 4, srcT + (size_t)(kb + lane) * 128 + gr0);
}

// GEMM over K=512, 32 chunks of 16k, 4-deep ring
__device__ void mma512(const float* __restrict__ srcT,
                       const float* __restrict__ ws,    // smem WT[k][32]
                       float* wbuf, ull acc[2],
                       int lane, int gr0, int cg) {
    stage_w(wbuf, srcT, 0, 0, lane, gr0); CP_COMMIT();
    stage_w(wbuf, srcT, 16, 1, lane, gr0); CP_COMMIT();
    stage_w(wbuf, srcT, 32, 2, lane, gr0); CP_COMMIT();
#pragma unroll 1
    for (int ch = 0; ch < 32; ch++) {
        if (ch < 29) {
            stage_w(wbuf, srcT, (ch + 3) * 16, (ch + 3) & 3, lane, gr0);
            CP_COMMIT();
            CP_WAIT(3);
        } else if (ch == 29) CP_WAIT(2);
        else if (ch == 30)   CP_WAIT(1);
        else                 CP_WAIT(0);
        __syncwarp();
        const float* cur = wbuf + (ch & 3) * 64;
        const float* wk = ws + ch * 16 * 32 + cg;
#pragma unroll
        for (int kk = 0; kk < 16; kk++) {
            ulonglong2 qa = *(const ulonglong2*)&cur[kk * 4];
            float w = wk[kk * 32];
            ull w2 = pk2(w, w);
            fma2(acc[0], qa.x, w2);
            fma2(acc[1], qa.y, w2);
        }
        __syncwarp();
    }
}

// INIT: 0 = token table, 1 = bias
template<int INIT, bool HAS_X, bool WRITE_PLAIN>
__device__ __forceinline__ void lstm_step(float* smraw,
                                          const float* __restrict__ tab,
                                          const float* __restrict__ bias,
                                          const float* __restrict__ xT,
                                          const float* __restrict__ Wx,
                                          const float* __restrict__ hT,
                                          const float* __restrict__ Wh,
                                          float* __restrict__ cs,
                                          float* __restrict__ hT_out,
                                          float* __restrict__ h_plain,
                                          int u0, int b0) {
    float* gbuf = smraw + S_GB;
    int*   tks  = (int*)(smraw + S_TKS);

    const int tid  = threadIdx.x;
    const int lane = tid & 31;
    const int warp = tid >> 5;
    const int r0   = warp * 4;               // local row base (0..60)
    const int gr0  = b0 + r0;                // global row base
    const int cg   = lane;                   // gate-col 0..31
    const int jc   = (cg >> 3) * HH + u0 + (cg & 7);
    float* wbuf = smraw + S_AS + warp * 256;

    ull acc[2];
    if (INIT == 0) {
        int t0 = tks[r0],     t1 = tks[r0 + 1];
        int t2 = tks[r0 + 2], t3 = tks[r0 + 3];
        acc[0] = pk2(tab[(size_t)t0 * GG + jc], tab[(size_t)t1 * GG + jc]);
        acc[1] = pk2(tab[(size_t)t2 * GG + jc], tab[(size_t)t3 * GG + jc]);
    } else {
        float bv = bias[jc];
        ull b2 = pk2(bv, bv);
        acc[0] = b2; acc[1] = b2;
    }

    if (HAS_X) mma512(xT, Wx, wbuf, acc, lane, gr0, cg);
    mma512(hT, Wh, wbuf, acc, lane, gr0, cg);

    *(ull*)&gbuf[cg * 66 + r0]     = acc[0];
    *(ull*)&gbuf[cg * 66 + r0 + 2] = acc[1];
    __syncthreads();

    // state update: thread -> (uu = tid>>6 in 0..7, b = tid&63)
    const int b  = tid & 63;
    const int uu = tid >> 6;
    {
        float gi = gbuf[(0 * 8 + uu) * 66 + b];
        float gf = gbuf[(1 * 8 + uu) * 66 + b];
        float gg = gbuf[(2 * 8 + uu) * 66 + b];
        float go = gbuf[(3 * 8 + uu) * 66 + b];
        float cold = cs[uu * 64 + b];
        float ig = 1.f / (1.f + expf(-gi));
        float fg = 1.f / (1.f + expf(-gf));
        float og = 1.f / (1.f + expf(-go));
        float cn = fg * cold + ig * tanhf(gg);
        float hn = og * tanhf(cn);
        cs[uu * 64 + b] = cn;
        hT_out[(u0 + uu) * 128 + b0 + b] = hn;
        if (WRITE_PLAIN) h_plain[(b0 + b) * HH + u0 + uu] = hn;
    }
    __syncthreads();
}

__device__ void fc_step(float* smraw, int t, const float* __restrict__ fc_b,
                        float* __restrict__ out) {
    float* gbuf = smraw + S_GB;
    const int b = blockIdx.x;
    const int tid = threadIdx.x;
    float* h1s  = gbuf;                 // 512
    float* part = gbuf + 512;           // 512
    float* rv   = gbuf + 1024;          // 256
    int*   ri   = (int*)(gbuf + 1280);  // 256

    h1s[tid] = g_h1[b * HH + tid];
    __syncthreads();

    const int v = tid & 255;
    const int half = tid >> 8;
    float acc = half ? 0.f : fc_b[v];
    const int k0 = half * 256;
#pragma unroll 8
    for (int k = k0; k < k0 + 256; k++) acc += h1s[k] * g_fcT[k * VV + v];
    part[half * 256 + v] = acc;
    __syncthreads();

    if (tid < 256) {
        float tot = part[tid] + part[256 + tid];
        out[((size_t)b * DSTEPS + t) * VV + tid] = tot;
        rv[tid] = tot; ri[tid] = tid;
    }
    __syncthreads();
    for (int offs = 128; offs > 0; offs >>= 1) {
        if (tid < offs) {
            float o = rv[tid + offs]; int oi = ri[tid + offs];
            if (o > rv[tid] || (o == rv[tid] && oi < ri[tid])) { rv[tid] = o; ri[tid] = oi; }
        }
        __syncthreads();
    }
    if (tid == 0) g_tok[b] = ri[0];
    __syncthreads();
}

// ---------------- the persistent kernel ----------------
__global__ void __launch_bounds__(NTH, 1)
seq2seq_persistent(const int* __restrict__ src,
                   const float* __restrict__ eWhh0,
                   const float* __restrict__ eWih1, const float* __restrict__ eWhh1,
                   const float* __restrict__ dWhh0,
                   const float* __restrict__ dWih1, const float* __restrict__ dWhh1,
                   const float* __restrict__ fc_b,
                   float* __restrict__ out) {
    extern __shared__ float smraw[];
    const int tid = threadIdx.x;
    const int cta = blockIdx.x;
    const int u0 = (cta >> 1) * 8;       // 64 unit-blocks of 8
    const int b0 = (cta & 1) * 64;       // 2 batch halves

    load_wsliceT(smraw + S_W0, eWhh0, u0);
    load_wsliceT(smraw + S_WX, eWih1, u0);
    load_wsliceT(smraw + S_WH, eWhh1, u0);
    for (int i = tid; i < 1024; i += NTH) smraw[S_CS0 + i] = 0.f;   // cs0 + cs1
    __syncthreads();

    // ===== fused encoder: L0 step tau + L1 step tau-1 per gbar interval =====
    const float* h0cur = g_h0TA;                 // zeros
    float* h1cur = g_h1TA;                       // zeros
    float* h1nxt = g_h1TB;
    for (int tau = 0; tau <= SS; tau++) {
        if (tau < SS) {
            if (tid < 64) ((int*)(smraw + S_TKS))[tid] = src[(b0 + tid) * SS + tau];
            __syncthreads();
            float* yT = g_y0T + (size_t)tau * HB;
            lstm_step<0, false, false>(smraw, g_tabE, nullptr, nullptr, nullptr,
                                       h0cur, smraw + S_W0, smraw + S_CS0,
                                       yT, nullptr, u0, b0);
            h0cur = yT;
        }
        if (tau >= 1) {
            const float* xT = g_y0T + (size_t)(tau - 1) * HB;
            lstm_step<1, true, false>(smraw, nullptr, g_b1e, xT, smraw + S_WX,
                                      h1cur, smraw + S_WH, smraw + S_CS1,
                                      h1nxt, nullptr, u0, b0);
            float* tt = h1cur; h1cur = h1nxt; h1nxt = tt;
        }
        gbar();
    }

    // ===== decoder (same geometry; cell states persist in smem) =====
    load_wsliceT(smraw + S_W0, dWhh0, u0);
    load_wsliceT(smraw + S_WX, dWih1, u0);
    load_wsliceT(smraw + S_WH, dWhh1, u0);
    __syncthreads();

    const float* h0c = g_y0T + (size_t)(SS - 1) * HB;   // encoder L0 final h
    float* h0bufs[2] = { g_h0TA, g_h0TB };
    for (int t = 0; t < DSTEPS; t++) {
        if (tid < 64) ((int*)(smraw + S_TKS))[tid] = g_tok[b0 + tid];
        __syncthreads();
        float* h0nxt = h0bufs[t & 1];
        lstm_step<0, false, false>(smraw, g_tabD, nullptr, nullptr, nullptr,
                                   h0c, smraw + S_W0, smraw + S_CS0,
                                   h0nxt, nullptr, u0, b0);
        gbar();
        lstm_step<1, true, true>(smraw, nullptr, g_b1d, h0nxt, smraw + S_WX,
                                 h1cur, smraw + S_WH, smraw + S_CS1,
                                 h1nxt, g_h1, u0, b0);
        gbar();
        fc_step(smraw, t, fc_b, out);
        gbar();
        h0c = h0nxt;
        float* tt = h1cur; h1cur = h1nxt; h1nxt = tt;
    }
}

// ---------------- host launch ----------------
extern "C" void kernel_launch(void* const* d_in, const int* in_sizes, int n_in,
                              void* d_out, int out_size) {
    const int*   src       = (const int*)d_in[0];
    const int*   trg       = (const int*)d_in[1];
    const float* enc_emb   = (const float*)d_in[2];
    const float* enc_w_ih0 = (const float*)d_in[3];
    const float* enc_w_hh0 = (const float*)d_in[4];
    const float* enc_b_ih0 = (const float*)d_in[5];
    const float* enc_b_hh0 = (const float*)d_in[6];
    const float* enc_w_ih1 = (const float*)d_in[7];
    const float* enc_w_hh1 = (const float*)d_in[8];
    const float* enc_b_ih1 = (const float*)d_in[9];
    const float* enc_b_hh1 = (const float*)d_in[10];
    const float* dec_emb   = (const float*)d_in[11];
    const float* dec_w_ih0 = (const float*)d_in[12];
    const float* dec_w_hh0 = (const float*)d_in[13];
    const float* dec_b_ih0 = (const float*)d_in[14];
    const float* dec_b_hh0 = (const float*)d_in[15];
    const float* dec_w_ih1 = (const float*)d_in[16];
    const float* dec_w_hh1 = (const float*)d_in[17];
    const float* dec_b_ih1 = (const float*)d_in[18];
    const float* dec_b_hh1 = (const float*)d_in[19];
    const float* fc_w      = (const float*)d_in[20];
    const float* fc_b      = (const float*)d_in[21];
    float* out = (float*)d_out;

    float* tabE; cudaGetSymbolAddress((void**)&tabE, g_tabE);
    float* tabD; cudaGetSymbolAddress((void**)&tabD, g_tabD);

    static int smem_set = 0;
    const int SMEM_BYTES = S_TOTAL * 4;   // 225792 B
    if (!smem_set) {
        cudaFuncSetAttribute(seq2seq_persistent,
                             cudaFuncAttributeMaxDynamicSharedMemorySize, SMEM_BYTES);
        smem_set = 1;
    }

    table_kernel<<<VV, 256>>>(tabE, enc_emb, enc_w_ih0, enc_b_ih0, enc_b_hh0);
    table_kernel<<<VV, 256>>>(tabD, dec_emb, dec_w_ih0, dec_b_ih0, dec_b_hh0);
    misc_init_kernel<<<256, 256>>>(trg, enc_b_ih1, enc_b_hh1, dec_b_ih1, dec_b_hh1, fc_w);

    seq2seq_persistent<<<NCTA, NTH, SMEM_BYTES>>>(
        src, enc_w_hh0, enc_w_ih1, enc_w_hh1,
        dec_w_hh0, dec_w_ih1, dec_w_hh1, fc_b, out);

    (void)in_sizes; (void)n_in; (void)out_size;
}